// round 1
// baseline (speedup 1.0000x reference)
#include <cuda_runtime.h>
#include <cstdint>

#define BB 256
#define TT 20
#define HH 512
#define WVV 301
#define FF 196
#define CC 512
#define VV 9871
#define XK 813   // WV + H  ==  WV + C

// ---------------- scratch (device globals; no allocation allowed) -------------
__device__ float g_xh[TT * BB * XK];     // [t][b][ x(301) | h(512) ]
__device__ float g_xc[TT * BB * XK];     // [t][b][ x(301) | ctx(512) ]
__device__ float g_ih[BB * XK];          // [b][ inp(301) | h(512) ]
__device__ float g_aw[BB * FF];          // attn logits -> softmax in place
__device__ float g_gz[BB * CC];          // gate logits (sigmoid applied on read)
__device__ float g_gates[BB * 4 * HH];   // lstm gate pre-activations
__device__ float g_cst[BB * HH];         // lstm cell state
__device__ float g_hs[TT * BB * HH];     // all hidden states (feeds vocab GEMM)
__device__ float g_Wl[4 * HH * XK];      // [Wih | Whh] concatenated
__device__ float g_bl[4 * HH];           // bih + bhh

// ---------------- setup kernels (run once per launch) -------------------------
__global__ void setup_x_kernel(const float* __restrict__ wv) {
    int idx = blockIdx.x * blockDim.x + threadIdx.x;
    const int total = TT * BB * WVV;
    if (idx >= total) return;
    int t = idx / (BB * WVV);
    int r = idx % (BB * WVV);
    int b = r / WVV, w = r % WVV;
    float v = (t == 0) ? 0.f : wv[(size_t)b * TT * WVV + (size_t)(t - 1) * WVV + w];
    size_t o = (size_t)(t * BB + b) * XK + w;
    g_xh[o] = v;
    g_xc[o] = v;
}

__global__ void setup_zero_kernel() {
    int idx = blockIdx.x * blockDim.x + threadIdx.x;
    if (idx >= BB * HH) return;
    int b = idx / HH, j = idx % HH;
    g_cst[idx] = 0.f;
    g_xh[(size_t)b * XK + WVV + j] = 0.f;   // h_0 = 0 for step 0
    g_ih[(size_t)b * XK + WVV + j] = 0.f;
}

__global__ void setup_w_kernel(const float* __restrict__ Wih, const float* __restrict__ Whh,
                               const float* __restrict__ bih, const float* __restrict__ bhh) {
    int idx = blockIdx.x * blockDim.x + threadIdx.x;
    if (idx < 4 * HH) g_bl[idx] = bih[idx] + bhh[idx];
    const int total = 4 * HH * XK;
    if (idx >= total) return;
    int j = idx / XK, k = idx % XK;
    g_Wl[idx] = (k < WVV) ? Wih[(size_t)j * WVV + k] : Whh[(size_t)j * HH + (k - WVV)];
}

// zero the split-K accumulation targets for one step
__global__ void zero_step_kernel() {
    int idx = blockIdx.x * blockDim.x + threadIdx.x;
    const int n1 = BB * FF, n2 = BB * CC, n3 = BB * 4 * HH, n4 = BB * WVV;
    if (idx >= n1 + n2 + n3 + n4) return;
    if (idx < n1) { g_aw[idx] = 0.f; return; }
    idx -= n1;
    if (idx < n2) { g_gz[idx] = 0.f; return; }
    idx -= n2;
    if (idx < n3) { g_gates[idx] = 0.f; return; }
    idx -= n3;
    int b = idx / WVV, w = idx % WVV;
    g_ih[(size_t)b * XK + w] = 0.f;
}

// ---------------- split-K SIMT GEMM:  C += A[256,K] * W[N,K]^T ---------------
// 64x64 tile, 256 threads, 4x4 per thread, atomicAdd epilogue.
__global__ void gemm_splitk(const float* __restrict__ A, int lda,
                            const float* __restrict__ W, int ldw,
                            float* __restrict__ C, int ldc,
                            int N, int K, int kchunk) {
    const int BK = 16;
    __shared__ float As[BK][64 + 4];
    __shared__ float Ws[BK][64 + 4];
    int bm = blockIdx.y * 64, bn = blockIdx.x * 64;
    int k0 = blockIdx.z * kchunk;
    int k1 = min(K, k0 + kchunk);
    int tid = threadIdx.x;
    int lk = tid & 15, lr = tid >> 4;   // loader: k-lane, row-group
    int wm = tid >> 4, wn = tid & 15;   // compute: row group, col group
    float acc[4][4] = {};
    for (int kt = k0; kt < k1; kt += BK) {
        int gk = kt + lk;
        bool kok = (gk < k1);
#pragma unroll
        for (int i = 0; i < 4; i++) {
            int r = lr + 16 * i;
            As[lk][r] = kok ? A[(size_t)(bm + r) * lda + gk] : 0.f;
            int gn = bn + r;
            Ws[lk][r] = (kok && gn < N) ? W[(size_t)gn * ldw + gk] : 0.f;
        }
        __syncthreads();
#pragma unroll
        for (int k = 0; k < BK; k++) {
            float a[4], w[4];
#pragma unroll
            for (int i = 0; i < 4; i++) a[i] = As[k][wm * 4 + i];
#pragma unroll
            for (int j = 0; j < 4; j++) w[j] = Ws[k][wn * 4 + j];
#pragma unroll
            for (int i = 0; i < 4; i++)
#pragma unroll
                for (int j = 0; j < 4; j++) acc[i][j] = fmaf(a[i], w[j], acc[i][j]);
        }
        __syncthreads();
    }
#pragma unroll
    for (int i = 0; i < 4; i++) {
        int gm = bm + wm * 4 + i;
#pragma unroll
        for (int j = 0; j < 4; j++) {
            int gn = bn + wn * 4 + j;
            if (gn < N) atomicAdd(&C[(size_t)gm * ldc + gn], acc[i][j]);
        }
    }
}

// ---------------- softmax over F=196 (adds attn bias), in place ---------------
__global__ void softmax_kernel(const float* __restrict__ bias) {
    __shared__ float red[256];
    int b = blockIdx.x, tid = threadIdx.x;
    float v = (tid < FF) ? g_aw[b * FF + tid] + bias[tid] : -3.0e38f;
    red[tid] = v;
    __syncthreads();
    for (int s = 128; s > 0; s >>= 1) {
        if (tid < s) red[tid] = fmaxf(red[tid], red[tid + s]);
        __syncthreads();
    }
    float mx = red[0];
    __syncthreads();
    float e = (tid < FF) ? expf(v - mx) : 0.f;
    red[tid] = e;
    __syncthreads();
    for (int s = 128; s > 0; s >>= 1) {
        if (tid < s) red[tid] += red[tid + s];
        __syncthreads();
    }
    if (tid < FF) g_aw[b * FF + tid] = e / red[0];
}

// -------- ctx[b,c] = sigmoid(gz[b,c]+gate_b[c]) * sum_f aw[b,f]*enc[b,c,f] ----
// writes into the ctx half of g_xc[t]
__global__ void ctx_kernel(const float* __restrict__ enc, const float* __restrict__ gate_b,
                           float* __restrict__ xc) {
    __shared__ __align__(16) float saw[196];
    int b = blockIdx.y;
    int c0 = blockIdx.x * 64;
    int tid = threadIdx.x;
    if (tid < FF) saw[tid] = g_aw[b * FF + tid];
    __syncthreads();
    int warp = tid >> 5, lane = tid & 31;
    const float4* sa4 = (const float4*)saw;   // 49 float4s
#pragma unroll
    for (int ci = 0; ci < 8; ci++) {
        int c = c0 + warp * 8 + ci;
        const float4* row = (const float4*)(enc + ((size_t)b * CC + c) * FF);
        float sum = 0.f;
        for (int f = lane; f < 49; f += 32) {
            float4 v = row[f], a = sa4[f];
            sum += v.x * a.x + v.y * a.y + v.z * a.z + v.w * a.w;
        }
#pragma unroll
        for (int o = 16; o > 0; o >>= 1) sum += __shfl_xor_sync(0xffffffffu, sum, o);
        if (lane == 0) {
            float gz = g_gz[b * CC + c] + gate_b[c];
            float gamma = 1.f / (1.f + expf(-gz));
            xc[(size_t)b * XK + WVV + c] = gamma * sum;
        }
    }
}

// ---------------- inp = relu(raw + comb_b) (in the inp half of g_ih) ----------
__global__ void finish_inp_kernel(const float* __restrict__ comb_b) {
    int idx = blockIdx.x * blockDim.x + threadIdx.x;
    if (idx >= BB * WVV) return;
    int b = idx / WVV, w = idx % WVV;
    size_t o = (size_t)b * XK + w;
    g_ih[o] = fmaxf(g_ih[o] + comb_b[w], 0.f);
}

// ---------------- LSTM cell elementwise ---------------------------------------
__global__ void lstm_elem_kernel(int t) {
    int idx = blockIdx.x * blockDim.x + threadIdx.x;
    if (idx >= BB * HH) return;
    int b = idx / HH, j = idx % HH;
    const float* gr = g_gates + (size_t)b * 4 * HH;
    float ii = gr[j] + g_bl[j];
    float ff = gr[HH + j] + g_bl[HH + j];
    float gg = gr[2 * HH + j] + g_bl[2 * HH + j];
    float oo = gr[3 * HH + j] + g_bl[3 * HH + j];
    float si = 1.f / (1.f + expf(-ii));
    float sf = 1.f / (1.f + expf(-ff));
    float so = 1.f / (1.f + expf(-oo));
    float cn = sf * g_cst[idx] + si * tanhf(gg);
    float hn = so * tanhf(cn);
    g_cst[idx] = cn;
    g_hs[(size_t)t * BB * HH + idx] = hn;
    g_ih[(size_t)b * XK + WVV + j] = hn;                              // h for lstm GEMM next step
    if (t + 1 < TT) g_xh[((size_t)(t + 1) * BB + b) * XK + WVV + j] = hn;  // h for attn/gate next step
}

// ------- vocab GEMM: out[b,t,:] = hs[t,b,:] @ vocab_W^T + vocab_b -------------
// 128x128x8 double-buffered SGEMM, M=5120, N=9871, K=512
__global__ void gemm_vocab(const float* __restrict__ A, const float* __restrict__ W,
                           const float* __restrict__ bias, float* __restrict__ out) {
    const int BK = 8, NT = 512 / BK;
    __shared__ float As[2][BK][128 + 4];
    __shared__ float Ws[2][BK][128 + 4];
    int bm = blockIdx.y * 128, bn = blockIdx.x * 128;
    int tid = threadIdx.x;
    int lr = tid >> 3;   // 0..31
    int lk = tid & 7;    // 0..7
    int wm = tid >> 4, wn = tid & 15;

    // load tile 0
#pragma unroll
    for (int i = 0; i < 4; i++) {
        int r = lr + 32 * i;
        As[0][lk][r] = A[(size_t)(bm + r) * 512 + lk];
        int gn = bn + r;
        Ws[0][lk][r] = (gn < VV) ? W[(size_t)gn * 512 + lk] : 0.f;
    }
    __syncthreads();

    float acc[8][8] = {};
    float ra[4], rw[4];
    for (int kt = 0; kt < NT; kt++) {
        int cur = kt & 1;
        if (kt + 1 < NT) {
            int gk = (kt + 1) * BK + lk;
#pragma unroll
            for (int i = 0; i < 4; i++) {
                int r = lr + 32 * i;
                ra[i] = A[(size_t)(bm + r) * 512 + gk];
                int gn = bn + r;
                rw[i] = (gn < VV) ? W[(size_t)gn * 512 + gk] : 0.f;
            }
        }
#pragma unroll
        for (int k = 0; k < BK; k++) {
            float a[8], w[8];
#pragma unroll
            for (int i = 0; i < 8; i++) a[i] = As[cur][k][wm * 8 + i];
#pragma unroll
            for (int j = 0; j < 8; j++) w[j] = Ws[cur][k][wn * 8 + j];
#pragma unroll
            for (int i = 0; i < 8; i++)
#pragma unroll
                for (int j = 0; j < 8; j++) acc[i][j] = fmaf(a[i], w[j], acc[i][j]);
        }
        if (kt + 1 < NT) {
#pragma unroll
            for (int i = 0; i < 4; i++) {
                int r = lr + 32 * i;
                As[cur ^ 1][lk][r] = ra[i];
                Ws[cur ^ 1][lk][r] = rw[i];
            }
            __syncthreads();
        }
    }

#pragma unroll
    for (int i = 0; i < 8; i++) {
        int m = bm + wm * 8 + i;          // m = t*256 + b
        int t = m >> 8, b = m & 255;
        float* crow = out + ((size_t)b * TT + t) * VV;
#pragma unroll
        for (int j = 0; j < 8; j++) {
            int gn = bn + wn * 8 + j;
            if (gn < VV) crow[gn] = acc[i][j] + bias[gn];
        }
    }
}

// ---------------- host launch --------------------------------------------------
extern "C" void kernel_launch(void* const* d_in, const int* in_sizes, int n_in,
                              void* d_out, int out_size) {
    const float* enc     = (const float*)d_in[0];
    const float* wv      = (const float*)d_in[1];
    const float* attn_W  = (const float*)d_in[2];
    const float* attn_b  = (const float*)d_in[3];
    const float* comb_W  = (const float*)d_in[4];
    const float* comb_b  = (const float*)d_in[5];
    const float* gate_W  = (const float*)d_in[6];
    const float* gate_b  = (const float*)d_in[7];
    const float* Wih     = (const float*)d_in[8];
    const float* Whh     = (const float*)d_in[9];
    const float* bih     = (const float*)d_in[10];
    const float* bhh     = (const float*)d_in[11];
    const float* vocab_W = (const float*)d_in[12];
    const float* vocab_b = (const float*)d_in[13];
    float* out = (float*)d_out;

    float *p_xh, *p_xc, *p_ih, *p_aw, *p_gz, *p_gates, *p_hs, *p_Wl;
    cudaGetSymbolAddress((void**)&p_xh, g_xh);
    cudaGetSymbolAddress((void**)&p_xc, g_xc);
    cudaGetSymbolAddress((void**)&p_ih, g_ih);
    cudaGetSymbolAddress((void**)&p_aw, g_aw);
    cudaGetSymbolAddress((void**)&p_gz, g_gz);
    cudaGetSymbolAddress((void**)&p_gates, g_gates);
    cudaGetSymbolAddress((void**)&p_hs, g_hs);
    cudaGetSymbolAddress((void**)&p_Wl, g_Wl);

    setup_x_kernel<<<(TT * BB * WVV + 255) / 256, 256>>>(wv);
    setup_zero_kernel<<<(BB * HH + 255) / 256, 256>>>();
    setup_w_kernel<<<(4 * HH * XK + 255) / 256, 256>>>(Wih, Whh, bih, bhh);

    const int zero_total = BB * FF + BB * CC + BB * 4 * HH + BB * WVV;
    for (int t = 0; t < TT; t++) {
        zero_step_kernel<<<(zero_total + 255) / 256, 256>>>();
        // attn logits: [x|h] @ attn_W^T     (M=256, N=196, K=813, S=8)
        gemm_splitk<<<dim3(4, 4, 8), 256>>>(p_xh + (size_t)t * BB * XK, XK,
                                            attn_W, XK, p_aw, FF, FF, XK, 102);
        // gate logits: h @ gate_W^T         (M=256, N=512, K=512, S=4)
        gemm_splitk<<<dim3(8, 4, 4), 256>>>(p_xh + (size_t)t * BB * XK + WVV, XK,
                                            gate_W, HH, p_gz, CC, CC, HH, 128);
        softmax_kernel<<<BB, 256>>>(attn_b);
        ctx_kernel<<<dim3(8, BB), 256>>>(enc, gate_b, p_xc + (size_t)t * BB * XK);
        // comb raw: [x|ctx] @ comb_W^T -> inp half of g_ih (M=256, N=301, K=813, S=8)
        gemm_splitk<<<dim3(5, 4, 8), 256>>>(p_xc + (size_t)t * BB * XK, XK,
                                            comb_W, XK, p_ih, XK, WVV, XK, 102);
        finish_inp_kernel<<<(BB * WVV + 255) / 256, 256>>>(comb_b);
        // lstm gates: [inp|h] @ [Wih|Whh]^T (M=256, N=2048, K=813, S=2)
        gemm_splitk<<<dim3(32, 4, 2), 256>>>(p_ih, XK, p_Wl, XK,
                                             p_gates, 4 * HH, 4 * HH, XK, 407);
        lstm_elem_kernel<<<(BB * HH + 255) / 256, 256>>>(t);
    }
    // vocab projection over all timesteps at once
    gemm_vocab<<<dim3((VV + 127) / 128, (TT * BB) / 128), 256>>>(p_hs, vocab_W, vocab_b, out);
}

// round 4
// speedup vs baseline: 1.2477x; 1.2477x over previous
#include <cuda_runtime.h>
#include <cuda_bf16.h>
#include <cstdint>

#define BB 256
#define TT 20
#define HH 512
#define WVV 301
#define FF 196
#define CC 512
#define VV 9871
#define XK 813   // WV + H == WV + C
#define NAG 708  // FF + CC combined attn+gate output
#define SAG 3
#define SCB 4
#define SLS 2

#define KP 1536          // 3 * 512, split-bf16 K
#define NPAD 9984        // 39 * 256
#define MROWS (TT * BB)  // 5120

// ---------------- scratch (device globals) ------------------------------------
__device__ float g_xh[TT * BB * XK];
__device__ float g_xc[TT * BB * XK];
__device__ float g_ih[BB * XK];
__device__ float g_ag_s[SAG * BB * NAG];
__device__ float g_comb_s[SCB * BB * WVV];
__device__ float g_gate_s[SLS * BB * 4 * HH];
__device__ float g_aw[BB * FF];
__device__ float g_cst[BB * HH];
__device__ float g_Wl[4 * HH * XK];
__device__ float g_Wag[NAG * XK];
__device__ float g_bl[4 * HH];
__device__ __nv_bfloat16 g_ap[(size_t)MROWS * KP];  // [Ah | Ah | Al]
__device__ __nv_bfloat16 g_wp[(size_t)NPAD * KP];   // [Wh | Wl | Wh]

// ---------------- setup kernels ------------------------------------------------
__global__ void setup_x_kernel(const float* __restrict__ wv) {
    int idx = blockIdx.x * blockDim.x + threadIdx.x;
    const int total = TT * BB * WVV;
    if (idx >= total) return;
    int t = idx / (BB * WVV);
    int r = idx % (BB * WVV);
    int b = r / WVV, w = r % WVV;
    float v = (t == 0) ? 0.f : wv[(size_t)b * TT * WVV + (size_t)(t - 1) * WVV + w];
    size_t o = (size_t)(t * BB + b) * XK + w;
    g_xh[o] = v;
    g_xc[o] = v;
}

__global__ void setup_zero_kernel() {
    int idx = blockIdx.x * blockDim.x + threadIdx.x;
    if (idx >= BB * HH) return;
    int b = idx / HH, j = idx % HH;
    g_cst[idx] = 0.f;
    g_xh[(size_t)b * XK + WVV + j] = 0.f;
    g_ih[(size_t)b * XK + WVV + j] = 0.f;
}

__global__ void setup_wl_kernel(const float* __restrict__ Wih, const float* __restrict__ Whh,
                                const float* __restrict__ bih, const float* __restrict__ bhh) {
    int idx = blockIdx.x * blockDim.x + threadIdx.x;
    if (idx < 4 * HH) g_bl[idx] = bih[idx] + bhh[idx];
    const int total = 4 * HH * XK;
    if (idx >= total) return;
    int j = idx / XK, k = idx % XK;
    g_Wl[idx] = (k < WVV) ? Wih[(size_t)j * WVV + k] : Whh[(size_t)j * HH + (k - WVV)];
}

__global__ void setup_wag_kernel(const float* __restrict__ attn_W, const float* __restrict__ gate_W) {
    int idx = blockIdx.x * blockDim.x + threadIdx.x;
    const int total = NAG * XK;
    if (idx >= total) return;
    int j = idx / XK, k = idx % XK;
    float v;
    if (j < FF) v = attn_W[(size_t)j * XK + k];
    else v = (k >= WVV) ? gate_W[(size_t)(j - FF) * HH + (k - WVV)] : 0.f;
    g_Wag[idx] = v;
}

// W'' = [Wh | Wl | Wh], padded rows zeroed
__global__ void setup_wp_kernel(const float* __restrict__ vw) {
    int idx = blockIdx.x * blockDim.x + threadIdx.x;
    const int total = NPAD * HH;
    if (idx >= total) return;
    int n = idx / HH, k = idx % HH;
    float v = (n < VV) ? vw[(size_t)n * HH + k] : 0.f;
    __nv_bfloat16 hi = __float2bfloat16(v);
    __nv_bfloat16 lo = __float2bfloat16(v - __bfloat162float(hi));
    size_t base = (size_t)n * KP;
    g_wp[base + k] = hi;
    g_wp[base + HH + k] = lo;
    g_wp[base + 2 * HH + k] = hi;
}

// ---------------- split-K SIMT GEMM (per-slice outputs, plain stores) ----------
__global__ void gemm_slice(const float* __restrict__ A, int lda,
                           const float* __restrict__ W, int ldw,
                           float* __restrict__ C, int ldc,
                           int N, int K, int kchunk, int sliceStride) {
    const int BK = 16;
    __shared__ float As[BK][64 + 4];
    __shared__ float Ws[BK][64 + 4];
    int bm = blockIdx.y * 64, bn = blockIdx.x * 64;
    int k0 = blockIdx.z * kchunk;
    int k1 = min(K, k0 + kchunk);
    int tid = threadIdx.x;
    int lk = tid & 15, lr = tid >> 4;
    int wm = tid >> 4, wn = tid & 15;
    float acc[4][4] = {};
    for (int kt = k0; kt < k1; kt += BK) {
        int gk = kt + lk;
        bool kok = (gk < k1);
#pragma unroll
        for (int i = 0; i < 4; i++) {
            int r = lr + 16 * i;
            As[lk][r] = kok ? A[(size_t)(bm + r) * lda + gk] : 0.f;
            int gn = bn + r;
            Ws[lk][r] = (kok && gn < N) ? W[(size_t)gn * ldw + gk] : 0.f;
        }
        __syncthreads();
#pragma unroll
        for (int k = 0; k < BK; k++) {
            float a[4], w[4];
#pragma unroll
            for (int i = 0; i < 4; i++) a[i] = As[k][wm * 4 + i];
#pragma unroll
            for (int j = 0; j < 4; j++) w[j] = Ws[k][wn * 4 + j];
#pragma unroll
            for (int i = 0; i < 4; i++)
#pragma unroll
                for (int j = 0; j < 4; j++) acc[i][j] = fmaf(a[i], w[j], acc[i][j]);
        }
        __syncthreads();
    }
    float* Cz = C + (size_t)blockIdx.z * sliceStride;
#pragma unroll
    for (int i = 0; i < 4; i++) {
        int gm = bm + wm * 4 + i;
#pragma unroll
        for (int j = 0; j < 4; j++) {
            int gn = bn + wn * 4 + j;
            if (gn < N) Cz[(size_t)gm * ldc + gn] = acc[i][j];
        }
    }
}

// ---------------- softmax over F=196 -------------------------------------------
__global__ void softmax_kernel(const float* __restrict__ bias) {
    __shared__ float red[256];
    int b = blockIdx.x, tid = threadIdx.x;
    float v = -3.0e38f;
    if (tid < FF) {
        v = bias[tid];
#pragma unroll
        for (int z = 0; z < SAG; z++) v += g_ag_s[(size_t)z * BB * NAG + (size_t)b * NAG + tid];
    }
    red[tid] = v;
    __syncthreads();
    for (int s = 128; s > 0; s >>= 1) {
        if (tid < s) red[tid] = fmaxf(red[tid], red[tid + s]);
        __syncthreads();
    }
    float mx = red[0];
    __syncthreads();
    float e = (tid < FF) ? expf(v - mx) : 0.f;
    red[tid] = e;
    __syncthreads();
    for (int s = 128; s > 0; s >>= 1) {
        if (tid < s) red[tid] += red[tid + s];
        __syncthreads();
    }
    if (tid < FF) g_aw[b * FF + tid] = e / red[0];
}

// ---- ctx kernel ----------------------------------------------------------------
__global__ void ctx_kernel(const float* __restrict__ enc, const float* __restrict__ gate_b,
                           float* __restrict__ xc) {
    __shared__ __align__(16) float saw[196];
    int b = blockIdx.y;
    int c0 = blockIdx.x * 64;
    int tid = threadIdx.x;
    if (tid < FF) saw[tid] = g_aw[b * FF + tid];
    __syncthreads();
    int warp = tid >> 5, lane = tid & 31;
    const float4* sa4 = (const float4*)saw;
#pragma unroll
    for (int ci = 0; ci < 8; ci++) {
        int c = c0 + warp * 8 + ci;
        const float4* row = (const float4*)(enc + ((size_t)b * CC + c) * FF);
        float sum = 0.f;
        for (int f = lane; f < 49; f += 32) {
            float4 v = row[f], a = sa4[f];
            sum += v.x * a.x + v.y * a.y + v.z * a.z + v.w * a.w;
        }
#pragma unroll
        for (int o = 16; o > 0; o >>= 1) sum += __shfl_xor_sync(0xffffffffu, sum, o);
        if (lane == 0) {
            float gz = gate_b[c];
#pragma unroll
            for (int z = 0; z < SAG; z++) gz += g_ag_s[(size_t)z * BB * NAG + (size_t)b * NAG + FF + c];
            float gamma = 1.f / (1.f + expf(-gz));
            xc[(size_t)b * XK + WVV + c] = gamma * sum;
        }
    }
}

// ---------------- inp = relu(sum comb slices + comb_b) --------------------------
__global__ void finish_inp_kernel(const float* __restrict__ comb_b) {
    int idx = blockIdx.x * blockDim.x + threadIdx.x;
    if (idx >= BB * WVV) return;
    int b = idx / WVV, w = idx % WVV;
    float s = comb_b[w];
#pragma unroll
    for (int z = 0; z < SCB; z++) s += g_comb_s[(size_t)z * BB * WVV + idx];
    g_ih[(size_t)b * XK + w] = fmaxf(s, 0.f);
}

// ---------------- LSTM cell elementwise; emits A'' rows for vocab GEMM ---------
__global__ void lstm_elem_kernel(int t) {
    int idx = blockIdx.x * blockDim.x + threadIdx.x;
    if (idx >= BB * HH) return;
    int b = idx / HH, j = idx % HH;
    const float* g0 = g_gate_s + (size_t)b * 4 * HH;
    const float* g1 = g0 + (size_t)BB * 4 * HH;
    float ii = g0[j] + g1[j] + g_bl[j];
    float ff = g0[HH + j] + g1[HH + j] + g_bl[HH + j];
    float gg = g0[2 * HH + j] + g1[2 * HH + j] + g_bl[2 * HH + j];
    float oo = g0[3 * HH + j] + g1[3 * HH + j] + g_bl[3 * HH + j];
    float si = 1.f / (1.f + expf(-ii));
    float sf = 1.f / (1.f + expf(-ff));
    float so = 1.f / (1.f + expf(-oo));
    float cn = sf * g_cst[idx] + si * tanhf(gg);
    float hn = so * tanhf(cn);
    g_cst[idx] = cn;
    g_ih[(size_t)b * XK + WVV + j] = hn;
    if (t + 1 < TT) g_xh[((size_t)(t + 1) * BB + b) * XK + WVV + j] = hn;
    // A'' row m = t*256 + b:  [hi | hi | lo]
    __nv_bfloat16 hi = __float2bfloat16(hn);
    __nv_bfloat16 lo = __float2bfloat16(hn - __bfloat162float(hi));
    size_t base = ((size_t)t * BB + b) * KP;
    g_ap[base + j] = hi;
    g_ap[base + HH + j] = hi;
    g_ap[base + 2 * HH + j] = lo;
}

// ===================== bf16 mma.sync vocab GEMM ================================
// out[b,t,:] = A''[m=t*256+b, :] @ W''[n, :]^T + vocab_b[n], K = 1536
// Block 128(M) x 256(N), 8 warps (2x4) of 64x64, BK=32, 3-stage cp.async.

#define VBM 128
#define VBN 256
#define VBK 32
#define NKT (KP / VBK)     // 48
#define STAGE_BYTES 24576  // A 8KB + B 16KB
#define ASZ 8192
#define NSTAGE 3
#define VSMEM (NSTAGE * STAGE_BYTES)

__device__ __forceinline__ uint32_t smem_u32(const void* p) {
    uint32_t a;
    asm("{ .reg .u64 t; cvta.to.shared.u64 t, %1; cvt.u32.u64 %0, t; }" : "=r"(a) : "l"(p));
    return a;
}
__device__ __forceinline__ void cp16(uint32_t saddr, const void* gptr) {
    asm volatile("cp.async.cg.shared.global [%0], [%1], 16;" :: "r"(saddr), "l"(gptr));
}
__device__ __forceinline__ void cp_commit() { asm volatile("cp.async.commit_group;"); }
template <int N>
__device__ __forceinline__ void cp_wait() { asm volatile("cp.async.wait_group %0;" :: "n"(N)); }

__device__ __forceinline__ void ldm_x4(uint32_t* r, uint32_t addr) {
    asm volatile("ldmatrix.sync.aligned.m8n8.x4.shared.b16 {%0,%1,%2,%3}, [%4];"
                 : "=r"(r[0]), "=r"(r[1]), "=r"(r[2]), "=r"(r[3]) : "r"(addr));
}
__device__ __forceinline__ void mma_bf16(float* c, const uint32_t* a, uint32_t b0, uint32_t b1) {
    asm volatile(
        "mma.sync.aligned.m16n8k16.row.col.f32.bf16.bf16.f32 "
        "{%0,%1,%2,%3}, {%4,%5,%6,%7}, {%8,%9}, {%0,%1,%2,%3};"
        : "+f"(c[0]), "+f"(c[1]), "+f"(c[2]), "+f"(c[3])
        : "r"(a[0]), "r"(a[1]), "r"(a[2]), "r"(a[3]), "r"(b0), "r"(b1));
}
// swizzled smem offset of 16B chunk (row, c) in a 64B-row tile
__device__ __forceinline__ uint32_t swz(int row, int c) {
    return (uint32_t)(row * 64 + ((c ^ ((row >> 1) & 3)) * 16));
}

__device__ __forceinline__ void issue_tile(const __nv_bfloat16* __restrict__ Ag,
                                           const __nv_bfloat16* __restrict__ Bg,
                                           uint32_t smb, int stage, int bm, int bn, int kt) {
    int tid = threadIdx.x;
    uint32_t abase = smb + stage * STAGE_BYTES;
    uint32_t bbase = abase + ASZ;
#pragma unroll
    for (int l = 0; l < 2; l++) {
        int idx = tid + 256 * l;
        int row = idx >> 2, c = idx & 3;
        cp16(abase + swz(row, c), Ag + (size_t)(bm + row) * KP + kt * VBK + c * 8);
    }
#pragma unroll
    for (int l = 0; l < 4; l++) {
        int idx = tid + 256 * l;
        int row = idx >> 2, c = idx & 3;
        cp16(bbase + swz(row, c), Bg + (size_t)(bn + row) * KP + kt * VBK + c * 8);
    }
    cp_commit();
}

__global__ void __launch_bounds__(256, 1)
gemm_vocab_mma(const __nv_bfloat16* __restrict__ Ag, const __nv_bfloat16* __restrict__ Bg,
               const float* __restrict__ bias, float* __restrict__ out) {
    extern __shared__ char sm[];
    uint32_t smb = smem_u32(sm);
    int tid = threadIdx.x;
    int wid = tid >> 5, lane = tid & 31;
    int wm = wid & 1, wn = wid >> 1;
    int bm = blockIdx.y * VBM, bn = blockIdx.x * VBN;

    // ldmatrix lane geometry
    int a_r = lane & 15;
    int a_c = lane >> 4;
    int b_r = (lane & 7) | (((lane >> 4) & 1) << 3);
    int b_c = (lane >> 3) & 1;

    float acc[4][8][4];
#pragma unroll
    for (int i = 0; i < 4; i++)
#pragma unroll
        for (int j = 0; j < 8; j++)
#pragma unroll
            for (int q = 0; q < 4; q++) acc[i][j][q] = 0.f;

    issue_tile(Ag, Bg, smb, 0, bm, bn, 0);
    issue_tile(Ag, Bg, smb, 1, bm, bn, 1);

    for (int kt = 0; kt < NKT; kt++) {
        cp_wait<1>();
        __syncthreads();
        if (kt + 2 < NKT) issue_tile(Ag, Bg, smb, (kt + 2) % NSTAGE, bm, bn, kt + 2);
        uint32_t abase = smb + (kt % NSTAGE) * STAGE_BYTES;
        uint32_t bbase = abase + ASZ;
#pragma unroll
        for (int s = 0; s < 2; s++) {
            uint32_t af[4][4], bf[4][4];
#pragma unroll
            for (int i = 0; i < 4; i++) {
                int row = wm * 64 + i * 16 + a_r;
                ldm_x4(af[i], abase + swz(row, s * 2 + a_c));
            }
#pragma unroll
            for (int jj = 0; jj < 4; jj++) {
                int row = wn * 64 + jj * 16 + b_r;
                ldm_x4(bf[jj], bbase + swz(row, s * 2 + b_c));
            }
#pragma unroll
            for (int i = 0; i < 4; i++)
#pragma unroll
                for (int jj = 0; jj < 4; jj++) {
                    mma_bf16(acc[i][2 * jj], af[i], bf[jj][0], bf[jj][1]);
                    mma_bf16(acc[i][2 * jj + 1], af[i], bf[jj][2], bf[jj][3]);
                }
        }
        __syncthreads();
    }

    // epilogue: scalar global stores with bias (out rows are only 4B-aligned:
    // VV is odd, so float2 stores would trap on odd rows)
#pragma unroll
    for (int i = 0; i < 4; i++) {
#pragma unroll
        for (int j = 0; j < 8; j++) {
            int gm0 = bm + wm * 64 + i * 16 + (lane >> 2);
            int gn = bn + wn * 64 + j * 8 + 2 * (lane & 3);
#pragma unroll
            for (int h = 0; h < 2; h++) {
                int gm = gm0 + h * 8;
                int t = gm >> 8, b = gm & 255;
                float* row = out + ((size_t)b * TT + t) * VV;
                float c0 = acc[i][j][2 * h], c1 = acc[i][j][2 * h + 1];
                if (gn < VV) row[gn] = c0 + bias[gn];
                if (gn + 1 < VV) row[gn + 1] = c1 + bias[gn + 1];
            }
        }
    }
}

// ---------------- host launch --------------------------------------------------
extern "C" void kernel_launch(void* const* d_in, const int* in_sizes, int n_in,
                              void* d_out, int out_size) {
    const float* enc     = (const float*)d_in[0];
    const float* wv      = (const float*)d_in[1];
    const float* attn_W  = (const float*)d_in[2];
    const float* attn_b  = (const float*)d_in[3];
    const float* comb_W  = (const float*)d_in[4];
    const float* comb_b  = (const float*)d_in[5];
    const float* gate_W  = (const float*)d_in[6];
    const float* gate_b  = (const float*)d_in[7];
    const float* Wih     = (const float*)d_in[8];
    const float* Whh     = (const float*)d_in[9];
    const float* bih     = (const float*)d_in[10];
    const float* bhh     = (const float*)d_in[11];
    const float* vocab_W = (const float*)d_in[12];
    const float* vocab_b = (const float*)d_in[13];
    float* out = (float*)d_out;

    float *p_xh, *p_xc, *p_ih, *p_ag, *p_comb, *p_gate, *p_Wl, *p_Wag;
    __nv_bfloat16 *p_ap, *p_wp;
    cudaGetSymbolAddress((void**)&p_xh, g_xh);
    cudaGetSymbolAddress((void**)&p_xc, g_xc);
    cudaGetSymbolAddress((void**)&p_ih, g_ih);
    cudaGetSymbolAddress((void**)&p_ag, g_ag_s);
    cudaGetSymbolAddress((void**)&p_comb, g_comb_s);
    cudaGetSymbolAddress((void**)&p_gate, g_gate_s);
    cudaGetSymbolAddress((void**)&p_Wl, g_Wl);
    cudaGetSymbolAddress((void**)&p_Wag, g_Wag);
    cudaGetSymbolAddress((void**)&p_ap, g_ap);
    cudaGetSymbolAddress((void**)&p_wp, g_wp);

    cudaFuncSetAttribute(gemm_vocab_mma, cudaFuncAttributeMaxDynamicSharedMemorySize, VSMEM);

    setup_x_kernel<<<(TT * BB * WVV + 255) / 256, 256>>>(wv);
    setup_zero_kernel<<<(BB * HH + 255) / 256, 256>>>();
    setup_wl_kernel<<<(4 * HH * XK + 255) / 256, 256>>>(Wih, Whh, bih, bhh);
    setup_wag_kernel<<<(NAG * XK + 255) / 256, 256>>>(attn_W, gate_W);
    setup_wp_kernel<<<(NPAD * HH + 255) / 256, 256>>>(vocab_W);

    for (int t = 0; t < TT; t++) {
        gemm_slice<<<dim3(12, 4, SAG), 256>>>(p_xh + (size_t)t * BB * XK, XK,
                                              p_Wag, XK, p_ag, NAG, NAG, XK, 271, BB * NAG);
        softmax_kernel<<<BB, 256>>>(attn_b);
        ctx_kernel<<<dim3(8, BB), 256>>>(enc, gate_b, p_xc + (size_t)t * BB * XK);
        gemm_slice<<<dim3(5, 4, SCB), 256>>>(p_xc + (size_t)t * BB * XK, XK,
                                             comb_W, XK, p_comb, WVV, WVV, XK, 204, BB * WVV);
        finish_inp_kernel<<<(BB * WVV + 255) / 256, 256>>>(comb_b);
        gemm_slice<<<dim3(32, 4, SLS), 256>>>(p_ih, XK, p_Wl, XK,
                                              p_gate, 4 * HH, 4 * HH, XK, 407, BB * 4 * HH);
        lstm_elem_kernel<<<(BB * HH + 255) / 256, 256>>>(t);
    }
    gemm_vocab_mma<<<dim3(NPAD / VBN, MROWS / VBM), 256, VSMEM>>>(p_ap, p_wp, vocab_b, out);
}